// round 17
// baseline (speedup 1.0000x reference)
#include <cuda_runtime.h>

typedef unsigned long long ull;

// Problem constants
constexpr int Tn = 1000, Dd = 64, Nn = 128, Bb = 1000;
constexpr int CS = 100;               // sim steps per chunk
constexpr int NCHUNK = Tn / CS;       // 10
constexpr int GRID = 148;             // 1 CTA per SM
constexpr int TPB = 256;
constexpr size_t ROWF = (size_t)Tn * Nn;
constexpr size_t REGION = (size_t)Bb * ROWF;

// KEY INSIGHT 1: all B rows identical (broadcast input, identical zero init).
// KEY INSIGHT 2 (R16, validated): chunked kernel pipeline — kernel k sims
// chunk k on CTA0 while CTAs 1-147 broadcast chunk k-1; kernel-boundary
// ordering gives fence-free visibility. 704us.
// R17: pipeline is sim-paced; revert sim warp to the leanest loop: register
// masks (no smem/barrier), serial-ffs walk, 4 interleaved word-loops feeding
// 2 independent packed-f32x2 accumulator pairs.

__device__ float g_inp_cur[Tn * Nn];
__device__ float g_spk[Tn * Nn];      // compact spikes (T, N)
__device__ float g_memh[Tn * Nn];     // compact membrane (T, N)
__device__ float g_trc[Nn];           // final trace (N)
// Sim state carried across chunks (lane-indexed float4)
__device__ float4 g_s_syn[32], g_s_mem[32], g_s_refr[32], g_s_rec[32], g_s_trc[32];

// ---------------------------------------------------------------------------
// Kernel A: input currents (1000x64 @ 64x128). ~5us.
// ---------------------------------------------------------------------------
__global__ void inp_cur_kernel(const float* __restrict__ sig,
                               const float* __restrict__ w_in) {
    int t = blockIdx.x, n = threadIdx.x;
    float acc = 0.f;
#pragma unroll
    for (int d = 0; d < Dd; ++d) acc += sig[t * Dd + d] * w_in[d * Nn + n];
    g_inp_cur[t * Nn + n] = acc;
}

__device__ __forceinline__ void fadd2(ull& acc, ull w) {
    asm("add.rn.f32x2 %0, %0, %1;" : "+l"(acc) : "l"(w));
}

// ---------------------------------------------------------------------------
// Single-warp sim of CS steps. Lane owns neurons 4l..4l+3 (bit l of ballot
// word j <-> neuron 4l+j). W row k: sWu[k*32 + lane] (16B/lane, conflict-free).
// ---------------------------------------------------------------------------
__device__ void run_sim_chunk(const float* __restrict__ sW, int chunk) {
    const int lane = threadIdx.x;     // 0..31
    float syn[4], mem[4], refr[4], rec[4], trc[4];
    if (chunk == 0) {
#pragma unroll
        for (int j = 0; j < 4; ++j) { syn[j]=mem[j]=refr[j]=rec[j]=trc[j]=0.f; }
    } else {
        const float4 a = g_s_syn[lane], b = g_s_mem[lane], c = g_s_refr[lane],
                     d = g_s_rec[lane], e = g_s_trc[lane];
        syn[0]=a.x; syn[1]=a.y; syn[2]=a.z; syn[3]=a.w;
        mem[0]=b.x; mem[1]=b.y; mem[2]=b.z; mem[3]=b.w;
        refr[0]=c.x; refr[1]=c.y; refr[2]=c.z; refr[3]=c.w;
        rec[0]=d.x; rec[1]=d.y; rec[2]=d.z; rec[3]=d.w;
        trc[0]=e.x; trc[1]=e.y; trc[2]=e.z; trc[3]=e.w;
    }

    const float4* __restrict__ xin = reinterpret_cast<const float4*>(g_inp_cur);
    float4* __restrict__ ospk = reinterpret_cast<float4*>(g_spk);
    float4* __restrict__ omem = reinterpret_cast<float4*>(g_memh);
    const ulonglong2* __restrict__ sWu =
        reinterpret_cast<const ulonglong2*>(sW);   // row k: sWu[k*32 + lane]
    const ulonglong2* __restrict__ wp = sWu + lane;

    const int t0 = chunk * CS, t1 = t0 + CS;
    float4 x = __ldg(&xin[t0 * 32 + lane]);

    for (int t = t0; t < t1; ++t) {
        const int tn = (t + 1 < Tn) ? (t + 1) : t;
        const float4 xn = __ldg(&xin[tn * 32 + lane]);
        const float xv[4] = {x.x, x.y, x.z, x.w};

        float s[4]; bool kk[4];
#pragma unroll
        for (int j = 0; j < 4; ++j) {
            syn[j] = syn[j] * 0.8f + (xv[j] + rec[j]);
            mem[j] = mem[j] * 0.9f + syn[j] * 0.1f;
            mem[j] = (refr[j] > 0.f) ? 0.f : mem[j];
            refr[j] = fmaxf(refr[j] - 1.f, 0.f);
            kk[j] = mem[j] > 1.0f;
            s[j] = kk[j] ? 1.f : 0.f;
            mem[j] = kk[j] ? 0.f : mem[j];
            refr[j] += s[j] * 2.f;
            trc[j] = trc[j] * 0.95f + s[j];
        }

        unsigned m0 = __ballot_sync(0xFFFFFFFFu, kk[0]);
        unsigned m1 = __ballot_sync(0xFFFFFFFFu, kk[1]);
        unsigned m2 = __ballot_sync(0xFFFFFFFFu, kk[2]);
        unsigned m3 = __ballot_sync(0xFFFFFFFFu, kk[3]);

        ospk[t * 32 + lane] = make_float4(s[0], s[1], s[2], s[3]);
        omem[t * 32 + lane] = make_float4(mem[0], mem[1], mem[2], mem[3]);

        // ---- sparse accumulate: rec = 0.95*rec + sum_{spiking k} W[k][cols]
        // neuron k = 4l + j -> wp[(4l+j)*32] ; two independent chain pairs
        // (words 0,2 -> A; words 1,3 -> B) interleave in the scheduler.
        ull aA0 = 0, aA1 = 0, aB0 = 0, aB1 = 0;
        while (m0) {
            const int l = __ffs(m0) - 1; m0 &= m0 - 1;
            const ulonglong2 w = wp[(l * 4 + 0) * 32];
            fadd2(aA0, w.x); fadd2(aA1, w.y);
        }
        while (m1) {
            const int l = __ffs(m1) - 1; m1 &= m1 - 1;
            const ulonglong2 w = wp[(l * 4 + 1) * 32];
            fadd2(aB0, w.x); fadd2(aB1, w.y);
        }
        while (m2) {
            const int l = __ffs(m2) - 1; m2 &= m2 - 1;
            const ulonglong2 w = wp[(l * 4 + 2) * 32];
            fadd2(aA0, w.x); fadd2(aA1, w.y);
        }
        while (m3) {
            const int l = __ffs(m3) - 1; m3 &= m3 - 1;
            const ulonglong2 w = wp[(l * 4 + 3) * 32];
            fadd2(aB0, w.x); fadd2(aB1, w.y);
        }
        fadd2(aA0, aB0); fadd2(aA1, aB1);

        rec[0] = rec[0] * 0.95f + __int_as_float((int)aA0);
        rec[1] = rec[1] * 0.95f + __int_as_float((int)(aA0 >> 32));
        rec[2] = rec[2] * 0.95f + __int_as_float((int)aA1);
        rec[3] = rec[3] * 0.95f + __int_as_float((int)(aA1 >> 32));

        x = xn;
    }

    // Save state for next chunk (always; deterministic under graph replay)
    g_s_syn[lane]  = make_float4(syn[0], syn[1], syn[2], syn[3]);
    g_s_mem[lane]  = make_float4(mem[0], mem[1], mem[2], mem[3]);
    g_s_refr[lane] = make_float4(refr[0], refr[1], refr[2], refr[3]);
    g_s_rec[lane]  = make_float4(rec[0], rec[1], rec[2], rec[3]);
    g_s_trc[lane]  = make_float4(trc[0], trc[1], trc[2], trc[3]);
    if (chunk == NCHUNK - 1)
        reinterpret_cast<float4*>(g_trc)[lane] =
            make_float4(trc[0], trc[1], trc[2], trc[3]);
}

// ---------------------------------------------------------------------------
// Broadcast chunk ck: 2000 (row, region) tasks; each = contiguous CS*512B
// copy from the compact buffer (L2-hot) into the destination row.
// ---------------------------------------------------------------------------
__device__ void bcast_chunk(float* __restrict__ out, int ck, int w, int nw,
                            int tid) {
    const int t0 = ck * CS;
    const float4* __restrict__ sspk =
        reinterpret_cast<const float4*>(g_spk) + t0 * 32;
    const float4* __restrict__ smem =
        reinterpret_cast<const float4*>(g_memh) + t0 * 32;
    float4* __restrict__ out4 = reinterpret_cast<float4*>(out);

    for (int tau = w; tau < 2 * Bb; tau += nw) {
        const int region = (tau >= Bb) ? 1 : 0;
        const int row = tau - region * Bb;
        const float4* __restrict__ src = region ? smem : sspk;
        float4* __restrict__ dst = out4 + (size_t)region * (REGION / 4) +
                                   (size_t)row * (ROWF / 4) + (size_t)t0 * 32;
        for (int i = tid; i < CS * 32; i += TPB)
            __stcs(&dst[i], __ldg(&src[i]));
    }
}

// ---------------------------------------------------------------------------
// Pipeline kernel k: CTA0 sims chunk k; CTAs 1..147 broadcast chunk k-1.
// ---------------------------------------------------------------------------
__global__ __launch_bounds__(TPB, 1)
void pipe_kernel(const float* __restrict__ Wrec, float* __restrict__ out,
                 int chunk) {
    extern __shared__ float sW[];   // 128*128 floats
    const int bid = blockIdx.x, tid = threadIdx.x;

    if (bid == 0) {
        for (int i = tid; i < (Nn * Nn) / 4; i += TPB)
            reinterpret_cast<float4*>(sW)[i] =
                reinterpret_cast<const float4*>(Wrec)[i];
        __syncthreads();
        if (tid < 32) run_sim_chunk(sW, chunk);
        return;
    }
    if (chunk > 0) bcast_chunk(out, chunk - 1, bid - 1, GRID - 1, tid);
}

// ---------------------------------------------------------------------------
// Final kernel: broadcast last chunk + trace rows.
// ---------------------------------------------------------------------------
__global__ __launch_bounds__(TPB, 1)
void final_kernel(float* __restrict__ out) {
    const int bid = blockIdx.x, tid = threadIdx.x;
    bcast_chunk(out, NCHUNK - 1, bid, GRID, tid);
    // trace: (B, N) rows
    if (tid < 32) {
        const float4 v = __ldg(&reinterpret_cast<const float4*>(g_trc)[tid]);
        float4* __restrict__ out4 = reinterpret_cast<float4*>(out);
        for (int r = bid; r < Bb; r += GRID)
            __stcs(&out4[2 * (REGION / 4) + (size_t)r * 32 + tid], v);
    }
}

// ---------------------------------------------------------------------------
// Harness entry
// ---------------------------------------------------------------------------
extern "C" void kernel_launch(void* const* d_in, const int* in_sizes, int n_in,
                              void* d_out, int out_size) {
    const float* sig   = (const float*)d_in[0];  // (1000, 64)
    const float* w_in  = (const float*)d_in[1];  // (64, 128)
    const float* w_rec = (const float*)d_in[2];  // (128, 128)
    float* out = (float*)d_out;
    (void)in_sizes; (void)n_in; (void)out_size;

    const int smem = Nn * Nn * (int)sizeof(float);  // 65536 B
    cudaFuncSetAttribute(pipe_kernel,
                         cudaFuncAttributeMaxDynamicSharedMemorySize, smem);

    inp_cur_kernel<<<Tn, Nn>>>(sig, w_in);
    for (int k = 0; k < NCHUNK; ++k)
        pipe_kernel<<<GRID, TPB, smem>>>(w_rec, out, k);
    final_kernel<<<GRID, TPB>>>(out);
}